// round 4
// baseline (speedup 1.0000x reference)
#include <cuda_runtime.h>
#include <cstdint>
#include <math.h>

#define NB 8
#define NS 2048
#define ND 512
#define BR 64
#define BC 64
#define DC 128
#define NTH 256

#define QS_STRIDE 516   // 512+4 : stride%32==4 -> conflict-free A-frag loads
#define KS_STRIDE 132   // 128+4 : conflict-free K-as-B loads
#define VS_STRIDE 136   // 128+8 : conflict-free V-as-B loads
#define PS_STRIDE 68    // 64+4  : conflict-free P-as-A loads

// shared memory layout (in floats)
#define OFF_Q   0
#define SZ_Q    (BR*QS_STRIDE)            // 33024
#define OFF_KV  (OFF_Q + SZ_Q)
#define SZ_KV   (BC*VS_STRIDE)            // 8704 (covers both K chunk 64*132 and V chunk 64*136)
#define OFF_P   (OFF_KV + SZ_KV)
#define SZ_P    (BR*PS_STRIDE)            // 4352
#define OFF_RED (OFF_P + SZ_P)
#define SZ_RED  (4*BR)                    // max partials [0,128), sum partials [128,256)
#define SMEM_FLOATS (OFF_RED + SZ_RED)    // 46336 floats = 185344 bytes

__device__ __forceinline__ uint32_t f2tf(float x) {
    uint32_t u;
    asm("cvt.rna.tf32.f32 %0, %1;" : "=r"(u) : "f"(x));
    return u;
}

// split fp32 into tf32 hi + tf32 lo (Markidis 3xTF32 decomposition)
__device__ __forceinline__ void split_tf(float x, uint32_t& hi, uint32_t& lo) {
    hi = f2tf(x);
    lo = f2tf(x - __uint_as_float(hi));
}

__device__ __forceinline__ uint32_t ldb(const float* p) {
    return __float_as_uint(*p);
}

__device__ __forceinline__ void mma8(float c[4],
                                     uint32_t a0, uint32_t a1, uint32_t a2, uint32_t a3,
                                     uint32_t b0, uint32_t b1) {
    asm volatile(
        "mma.sync.aligned.m16n8k8.row.col.f32.tf32.tf32.f32 "
        "{%0,%1,%2,%3},{%4,%5,%6,%7},{%8,%9},{%0,%1,%2,%3};\n"
        : "+f"(c[0]), "+f"(c[1]), "+f"(c[2]), "+f"(c[3])
        : "r"(a0), "r"(a1), "r"(a2), "r"(a3), "r"(b0), "r"(b1));
}

extern __shared__ float sm[];

__global__ void __launch_bounds__(NTH, 1)
attn_flash_tf32(const float* __restrict__ Q,
                const float* __restrict__ K,
                const float* __restrict__ V,
                float* __restrict__ O) {
    const int b   = blockIdx.y;
    const int q0  = blockIdx.x * BR;
    const int tid = threadIdx.x;
    const int wid = tid >> 5;
    const int lane = tid & 31;
    const int wm = wid & 3;          // warp row: 4 warps over 64 rows (16 each)
    const int wn = wid >> 2;         // warp col: 2 warps over N
    const int g = lane >> 2;         // groupID
    const int t = lane & 3;          // threadID-in-group
    const int RM = wm * 16;

    const float* Qb = Q + ((size_t)b * NS + q0) * ND;
    const float* Kb = K + (size_t)b * NS * ND;
    const float* Vb = V + (size_t)b * NS * ND;

    float* Qs  = sm + OFF_Q;
    float* KVs = sm + OFF_KV;
    float* Ps  = sm + OFF_P;
    float* red = sm + OFF_RED;

    // ---- load Q tile (64x512) into smem as RAW fp32 (split to tf32 at frag load) ----
    #pragma unroll
    for (int i = 0; i < (BR * ND / 4) / NTH; i++) {   // 32 iters
        int idx = tid + i * NTH;
        int row = idx >> 7;          // 128 float4 per row
        int c4  = idx & 127;
        float4 v = *reinterpret_cast<const float4*>(Qb + (size_t)row * ND + c4 * 4);
        *reinterpret_cast<float4*>(Qs + row * QS_STRIDE + c4 * 4) = v;
    }

    // output accumulators: o[dc][n8][4]; rows RM+g, RM+g+8; cols dc*128 + wn*64 + n8*8 + 2t{,+1}
    float o[4][8][4];
    #pragma unroll
    for (int a = 0; a < 4; a++)
        #pragma unroll
        for (int n = 0; n < 8; n++)
            #pragma unroll
            for (int c = 0; c < 4; c++) o[a][n][c] = 0.f;

    float m_r[2] = {-INFINITY, -INFINITY};
    float l_r[2] = {0.f, 0.f};

    for (int kt = 0; kt < NS / BC; kt++) {
        const int kv0 = kt * BC;

        // ---- S = Q K^T for this KV tile (64x64), contraction over D in 4 chunks ----
        float sc[4][4];
        #pragma unroll
        for (int n = 0; n < 4; n++)
            #pragma unroll
            for (int c = 0; c < 4; c++) sc[n][c] = 0.f;

        for (int dc = 0; dc < ND / DC; dc++) {
            __syncthreads();   // previous consumers of KVs / red done
            #pragma unroll
            for (int i = 0; i < (BC * DC / 4) / NTH; i++) {   // 8 iters
                int idx = tid + i * NTH;
                int row = idx >> 5;     // 32 float4 per row
                int c4  = idx & 31;
                float4 v = *reinterpret_cast<const float4*>(
                    Kb + (size_t)(kv0 + row) * ND + dc * DC + c4 * 4);
                *reinterpret_cast<float4*>(KVs + row * KS_STRIDE + c4 * 4) = v;  // raw fp32
            }
            __syncthreads();

            #pragma unroll
            for (int kk = 0; kk < DC; kk += 8) {
                const float* qrow0 = Qs + (RM + g) * QS_STRIDE + dc * DC + kk + t;
                const float* qrow1 = Qs + (RM + g + 8) * QS_STRIDE + dc * DC + kk + t;
                uint32_t ah[4], al[4];
                split_tf(qrow0[0], ah[0], al[0]);
                split_tf(qrow1[0], ah[1], al[1]);
                split_tf(qrow0[4], ah[2], al[2]);
                split_tf(qrow1[4], ah[3], al[3]);
                #pragma unroll
                for (int n8 = 0; n8 < 4; n8++) {
                    int col = wn * 32 + n8 * 8 + g;   // kv index within tile
                    uint32_t bh0, bl0, bh1, bl1;
                    split_tf(KVs[col * KS_STRIDE + kk + t],     bh0, bl0);
                    split_tf(KVs[col * KS_STRIDE + kk + t + 4], bh1, bl1);
                    // 3xTF32: hi*hi + lo*hi + hi*lo
                    mma8(sc[n8], ah[0], ah[1], ah[2], ah[3], bh0, bh1);
                    mma8(sc[n8], al[0], al[1], al[2], al[3], bh0, bh1);
                    mma8(sc[n8], ah[0], ah[1], ah[2], ah[3], bl0, bl1);
                }
            }
        }

        // ---- online softmax: row max ----
        #pragma unroll
        for (int j = 0; j < 2; j++) {
            float mx = sc[0][2 * j];
            mx = fmaxf(mx, sc[0][2 * j + 1]);
            #pragma unroll
            for (int n8 = 1; n8 < 4; n8++) {
                mx = fmaxf(mx, sc[n8][2 * j]);
                mx = fmaxf(mx, sc[n8][2 * j + 1]);
            }
            mx = fmaxf(mx, __shfl_xor_sync(0xffffffffu, mx, 1));
            mx = fmaxf(mx, __shfl_xor_sync(0xffffffffu, mx, 2));
            if (t == 0) red[wn * BR + RM + g + 8 * j] = mx;
        }
        __syncthreads();

        float scale[2];
        #pragma unroll
        for (int j = 0; j < 2; j++) {
            int row = RM + g + 8 * j;
            float mt = fmaxf(red[row], red[BR + row]);
            float mnew = fmaxf(m_r[j], mt);
            scale[j] = __expf(m_r[j] - mnew);
            m_r[j] = mnew;
        }

        // ---- exponentiate, row-sum, write P (tf32) to smem ----
        float lsum_loc[2] = {0.f, 0.f};
        #pragma unroll
        for (int n8 = 0; n8 < 4; n8++) {
            #pragma unroll
            for (int j = 0; j < 2; j++) {
                float p0 = __expf(sc[n8][2 * j]     - m_r[j]);
                float p1 = __expf(sc[n8][2 * j + 1] - m_r[j]);
                lsum_loc[j] += p0 + p1;
                int row = RM + g + 8 * j;
                int col = wn * 32 + n8 * 8 + 2 * t;
                uint2 u = make_uint2(f2tf(p0), f2tf(p1));
                *reinterpret_cast<uint2*>(Ps + row * PS_STRIDE + col) = u;
            }
        }
        #pragma unroll
        for (int j = 0; j < 2; j++) {
            lsum_loc[j] += __shfl_xor_sync(0xffffffffu, lsum_loc[j], 1);
            lsum_loc[j] += __shfl_xor_sync(0xffffffffu, lsum_loc[j], 2);
            if (t == 0) red[2 * BR + wn * BR + RM + g + 8 * j] = lsum_loc[j];
        }
        __syncthreads();   // Ps + sum partials visible

        #pragma unroll
        for (int j = 0; j < 2; j++) {
            int row = RM + g + 8 * j;
            float ls = red[2 * BR + row] + red[3 * BR + row];
            l_r[j] = l_r[j] * scale[j] + ls;
        }

        // rescale existing O accumulators
        #pragma unroll
        for (int a = 0; a < 4; a++)
            #pragma unroll
            for (int n = 0; n < 8; n++) {
                o[a][n][0] *= scale[0];
                o[a][n][1] *= scale[0];
                o[a][n][2] *= scale[1];
                o[a][n][3] *= scale[1];
            }

        // ---- O += P V, streaming V in 4 D-chunks (single tf32: error floor ~3e-4) ----
        for (int dc = 0; dc < ND / DC; dc++) {
            __syncthreads();   // prior users of KVs done
            #pragma unroll
            for (int i = 0; i < (BC * DC / 4) / NTH; i++) {   // 8 iters
                int idx = tid + i * NTH;
                int row = idx >> 5;
                int c4  = idx & 31;
                float4 v = *reinterpret_cast<const float4*>(
                    Vb + (size_t)(kv0 + row) * ND + dc * DC + c4 * 4);
                uint4 u;
                u.x = f2tf(v.x); u.y = f2tf(v.y); u.z = f2tf(v.z); u.w = f2tf(v.w);
                *reinterpret_cast<uint4*>(KVs + row * VS_STRIDE + c4 * 4) = u;
            }
            __syncthreads();

            #pragma unroll
            for (int kk = 0; kk < BC; kk += 8) {
                const float* prow0 = Ps + (RM + g) * PS_STRIDE + kk + t;
                const float* prow1 = Ps + (RM + g + 8) * PS_STRIDE + kk + t;
                uint32_t a0 = ldb(prow0);
                uint32_t a1 = ldb(prow1);
                uint32_t a2 = ldb(prow0 + 4);
                uint32_t a3 = ldb(prow1 + 4);
                #pragma unroll
                for (int n8 = 0; n8 < 8; n8++) {
                    int col = wn * 64 + n8 * 8 + g;
                    uint32_t b0 = ldb(KVs + (kk + t) * VS_STRIDE + col);
                    uint32_t b1 = ldb(KVs + (kk + t + 4) * VS_STRIDE + col);
                    mma8(o[dc][n8], a0, a1, a2, a3, b0, b1);
                }
            }
        }
    }

    // ---- normalize and write output ----
    float inv[2] = {1.f / l_r[0], 1.f / l_r[1]};
    float* Ob = O + ((size_t)b * NS + q0) * ND;
    #pragma unroll
    for (int dc = 0; dc < 4; dc++)
        #pragma unroll
        for (int n8 = 0; n8 < 8; n8++)
            #pragma unroll
            for (int j = 0; j < 2; j++) {
                int row = RM + g + 8 * j;
                int col = dc * DC + wn * 64 + n8 * 8 + 2 * t;
                float2 v = make_float2(o[dc][n8][2 * j] * inv[j],
                                       o[dc][n8][2 * j + 1] * inv[j]);
                *reinterpret_cast<float2*>(Ob + (size_t)row * ND + col) = v;
            }
}

extern "C" void kernel_launch(void* const* d_in, const int* in_sizes, int n_in,
                              void* d_out, int out_size) {
    const float* q = (const float*)d_in[0];
    const float* k = (const float*)d_in[1];
    const float* v = (const float*)d_in[2];
    float* o = (float*)d_out;

    const int smem_bytes = SMEM_FLOATS * 4;   // 185344
    cudaFuncSetAttribute(attn_flash_tf32,
                         cudaFuncAttributeMaxDynamicSharedMemorySize, smem_bytes);
    dim3 grid(NS / BR, NB);
    attn_flash_tf32<<<grid, NTH, smem_bytes>>>(q, k, v, o);
}

// round 5
// speedup vs baseline: 1.2328x; 1.2328x over previous
#include <cuda_runtime.h>
#include <cstdint>
#include <math.h>

#define NB 8
#define NS 2048
#define ND 512
#define BR 64
#define BC 64
#define DC 128
#define NTH 256

#define QS_STRIDE 516   // 512+4 : stride%32==4 -> conflict-free A-frag loads
#define KS_STRIDE 132   // 128+4 : conflict-free K-as-B loads
#define VS_STRIDE 136   // 128+8 : conflict-free V-as-B loads
#define PS_STRIDE 68    // 64+4  : conflict-free P-as-A loads

// shared memory layout (in floats)
#define OFF_Q   0
#define SZ_Q    (BR*QS_STRIDE)            // 33024
#define SZ_KVB  (BC*VS_STRIDE)            // 8704 floats per buffer (max of K/V chunk)
#define OFF_KV  (OFF_Q + SZ_Q)
#define SZ_KV   (2*SZ_KVB)                // 17408 (double-buffered)
#define OFF_P   (OFF_KV + SZ_KV)
#define SZ_P    (BR*PS_STRIDE)            // 4352
#define OFF_RED (OFF_P + SZ_P)
#define SZ_RED  (4*BR)
#define SMEM_FLOATS (OFF_RED + SZ_RED)    // 55040 floats = 220160 bytes

#define N_CHUNKS (NB ? ((NS/BC)*8) : 0)   // 32 tiles * (4 K + 4 V) = 256 per CTA

__device__ __forceinline__ uint32_t f2tf(float x) {
    uint32_t u;
    asm("cvt.rna.tf32.f32 %0, %1;" : "=r"(u) : "f"(x));
    return u;
}

__device__ __forceinline__ uint32_t ldb(const float* p) {
    return __float_as_uint(*p);
}

__device__ __forceinline__ void mma8(float c[4],
                                     uint32_t a0, uint32_t a1, uint32_t a2, uint32_t a3,
                                     uint32_t b0, uint32_t b1) {
    asm volatile(
        "mma.sync.aligned.m16n8k8.row.col.f32.tf32.tf32.f32 "
        "{%0,%1,%2,%3},{%4,%5,%6,%7},{%8,%9},{%0,%1,%2,%3};\n"
        : "+f"(c[0]), "+f"(c[1]), "+f"(c[2]), "+f"(c[3])
        : "r"(a0), "r"(a1), "r"(a2), "r"(a3), "r"(b0), "r"(b1));
}

extern __shared__ float sm[];

// Issue async copy of flattened chunk index c (guarded), always commit a group
// so cp.async.wait_group counting stays uniform at the tail.
__device__ __forceinline__ void issue_chunk(int c, const float* Kb, const float* Vb,
                                            float* kvbase, int tid) {
    if (c < N_CHUNKS) {
        const int kt = c >> 3;
        const int ph = (c >> 2) & 1;          // 0 = K, 1 = V
        const int dc = c & 3;
        const float* src = (ph ? Vb : Kb) + (size_t)(kt * BC) * ND + dc * DC;
        const int stride = ph ? VS_STRIDE : KS_STRIDE;
        float* dst = kvbase + (c & 1) * SZ_KVB;
        #pragma unroll
        for (int i = 0; i < 8; i++) {
            int idx = tid + i * NTH;
            int row = idx >> 5;               // 32 float4 per row
            int c4  = idx & 31;
            const float* g = src + (size_t)row * ND + c4 * 4;
            uint32_t saddr = (uint32_t)__cvta_generic_to_shared(dst + row * stride + c4 * 4);
            asm volatile("cp.async.cg.shared.global [%0], [%1], 16;\n"
                         :: "r"(saddr), "l"(g));
        }
    }
    asm volatile("cp.async.commit_group;\n");
}

__device__ __forceinline__ void wait_prev() {
    asm volatile("cp.async.wait_group 1;\n" ::: "memory");
}

__global__ void __launch_bounds__(NTH, 1)
attn_flash_tf32(const float* __restrict__ Q,
                const float* __restrict__ K,
                const float* __restrict__ V,
                float* __restrict__ O) {
    const int b   = blockIdx.y;
    const int q0  = blockIdx.x * BR;
    const int tid = threadIdx.x;
    const int wid = tid >> 5;
    const int lane = tid & 31;
    const int wm = wid & 3;          // warp row: 4 warps over 64 rows (16 each)
    const int wn = wid >> 2;         // warp col: 2 warps over N
    const int g = lane >> 2;         // groupID
    const int t = lane & 3;          // threadID-in-group
    const int RM = wm * 16;

    const float* Qb = Q + ((size_t)b * NS + q0) * ND;
    const float* Kb = K + (size_t)b * NS * ND;
    const float* Vb = V + (size_t)b * NS * ND;

    float* Qs  = sm + OFF_Q;
    float* KVb = sm + OFF_KV;
    float* Ps  = sm + OFF_P;
    float* red = sm + OFF_RED;

    // kick off the async pipeline before the (long) Q load
    issue_chunk(0, Kb, Vb, KVb, tid);
    issue_chunk(1, Kb, Vb, KVb, tid);

    // ---- load Q tile (64x512) into smem as RAW fp32 (split to tf32 at frag load) ----
    #pragma unroll
    for (int i = 0; i < (BR * ND / 4) / NTH; i++) {   // 32 iters
        int idx = tid + i * NTH;
        int row = idx >> 7;          // 128 float4 per row
        int c4  = idx & 127;
        float4 v = *reinterpret_cast<const float4*>(Qb + (size_t)row * ND + c4 * 4);
        *reinterpret_cast<float4*>(Qs + row * QS_STRIDE + c4 * 4) = v;
    }

    // output accumulators
    float o[4][8][4];
    #pragma unroll
    for (int a = 0; a < 4; a++)
        #pragma unroll
        for (int n = 0; n < 8; n++)
            #pragma unroll
            for (int c = 0; c < 4; c++) o[a][n][c] = 0.f;

    float m_r[2] = {-INFINITY, -INFINITY};
    float l_r[2] = {0.f, 0.f};

    for (int kt = 0; kt < NS / BC; kt++) {
        // ---- S = Q K^T (64x64), contraction over D in 4 async-pipelined chunks ----
        float sc[4][4];
        #pragma unroll
        for (int n = 0; n < 4; n++)
            #pragma unroll
            for (int c = 0; c < 4; c++) sc[n][c] = 0.f;

        for (int dc = 0; dc < ND / DC; dc++) {
            const int cc = kt * 8 + dc;
            wait_prev();
            __syncthreads();
            const float* Kc = KVb + (cc & 1) * SZ_KVB;

            #pragma unroll
            for (int kk = 0; kk < DC; kk += 8) {
                const float* qrow0 = Qs + (RM + g) * QS_STRIDE + dc * DC + kk + t;
                const float* qrow1 = Qs + (RM + g + 8) * QS_STRIDE + dc * DC + kk + t;
                uint32_t ah[4], al[4];
                {
                    float x0 = qrow0[0], x1 = qrow1[0], x2 = qrow0[4], x3 = qrow1[4];
                    ah[0] = f2tf(x0); al[0] = __float_as_uint(x0 - __uint_as_float(ah[0]));
                    ah[1] = f2tf(x1); al[1] = __float_as_uint(x1 - __uint_as_float(ah[1]));
                    ah[2] = f2tf(x2); al[2] = __float_as_uint(x2 - __uint_as_float(ah[2]));
                    ah[3] = f2tf(x3); al[3] = __float_as_uint(x3 - __uint_as_float(ah[3]));
                }
                #pragma unroll
                for (int n8 = 0; n8 < 4; n8++) {
                    int col = wn * 32 + n8 * 8 + g;   // kv index within tile
                    float k0 = Kc[col * KS_STRIDE + kk + t];
                    float k1 = Kc[col * KS_STRIDE + kk + t + 4];
                    uint32_t bh0 = f2tf(k0);
                    uint32_t bh1 = f2tf(k1);
                    uint32_t bl0 = __float_as_uint(k0 - __uint_as_float(bh0));
                    uint32_t bl1 = __float_as_uint(k1 - __uint_as_float(bh1));
                    // 3xTF32: hi*hi + lo*hi + hi*lo (lo fed raw; HW truncates)
                    mma8(sc[n8], ah[0], ah[1], ah[2], ah[3], bh0, bh1);
                    mma8(sc[n8], al[0], al[1], al[2], al[3], bh0, bh1);
                    mma8(sc[n8], ah[0], ah[1], ah[2], ah[3], bl0, bl1);
                }
            }
            __syncthreads();
            issue_chunk(cc + 2, Kb, Vb, KVb, tid);
        }

        // ---- online softmax: row max ----
        #pragma unroll
        for (int j = 0; j < 2; j++) {
            float mx = sc[0][2 * j];
            mx = fmaxf(mx, sc[0][2 * j + 1]);
            #pragma unroll
            for (int n8 = 1; n8 < 4; n8++) {
                mx = fmaxf(mx, sc[n8][2 * j]);
                mx = fmaxf(mx, sc[n8][2 * j + 1]);
            }
            mx = fmaxf(mx, __shfl_xor_sync(0xffffffffu, mx, 1));
            mx = fmaxf(mx, __shfl_xor_sync(0xffffffffu, mx, 2));
            if (t == 0) red[wn * BR + RM + g + 8 * j] = mx;
        }
        __syncthreads();

        float scale[2];
        #pragma unroll
        for (int j = 0; j < 2; j++) {
            int row = RM + g + 8 * j;
            float mt = fmaxf(red[row], red[BR + row]);
            float mnew = fmaxf(m_r[j], mt);
            scale[j] = __expf(m_r[j] - mnew);
            m_r[j] = mnew;
        }

        // ---- exponentiate, row-sum over the ROUNDED values, write P (tf32) ----
        float lsum_loc[2] = {0.f, 0.f};
        #pragma unroll
        for (int n8 = 0; n8 < 4; n8++) {
            #pragma unroll
            for (int j = 0; j < 2; j++) {
                float p0 = __expf(sc[n8][2 * j]     - m_r[j]);
                float p1 = __expf(sc[n8][2 * j + 1] - m_r[j]);
                uint32_t u0 = f2tf(p0), u1 = f2tf(p1);
                lsum_loc[j] += __uint_as_float(u0) + __uint_as_float(u1);
                int row = RM + g + 8 * j;
                int col = wn * 32 + n8 * 8 + 2 * t;
                *reinterpret_cast<uint2*>(Ps + row * PS_STRIDE + col) = make_uint2(u0, u1);
            }
        }
        #pragma unroll
        for (int j = 0; j < 2; j++) {
            lsum_loc[j] += __shfl_xor_sync(0xffffffffu, lsum_loc[j], 1);
            lsum_loc[j] += __shfl_xor_sync(0xffffffffu, lsum_loc[j], 2);
            if (t == 0) red[2 * BR + wn * BR + RM + g + 8 * j] = lsum_loc[j];
        }
        __syncthreads();   // Ps + sum partials visible

        #pragma unroll
        for (int j = 0; j < 2; j++) {
            int row = RM + g + 8 * j;
            float ls = red[2 * BR + row] + red[3 * BR + row];
            l_r[j] = l_r[j] * scale[j] + ls;
        }

        // rescale existing O accumulators
        #pragma unroll
        for (int a = 0; a < 4; a++)
            #pragma unroll
            for (int n = 0; n < 8; n++) {
                o[a][n][0] *= scale[0];
                o[a][n][1] *= scale[0];
                o[a][n][2] *= scale[1];
                o[a][n][3] *= scale[1];
            }

        // ---- O += P V, async-pipelined V chunks (V fed raw; HW tf32 truncation) ----
        for (int dc = 0; dc < ND / DC; dc++) {
            const int cc = kt * 8 + 4 + dc;
            wait_prev();
            __syncthreads();
            const float* Vc = KVb + (cc & 1) * SZ_KVB;

            #pragma unroll
            for (int kk = 0; kk < BC; kk += 8) {
                const float* prow0 = Ps + (RM + g) * PS_STRIDE + kk + t;
                const float* prow1 = Ps + (RM + g + 8) * PS_STRIDE + kk + t;
                uint32_t a0 = ldb(prow0);
                uint32_t a1 = ldb(prow1);
                uint32_t a2 = ldb(prow0 + 4);
                uint32_t a3 = ldb(prow1 + 4);
                #pragma unroll
                for (int n8 = 0; n8 < 8; n8++) {
                    int col = wn * 64 + n8 * 8 + g;
                    uint32_t b0 = ldb(Vc + (kk + t) * VS_STRIDE + col);
                    uint32_t b1 = ldb(Vc + (kk + t + 4) * VS_STRIDE + col);
                    mma8(o[dc][n8], a0, a1, a2, a3, b0, b1);
                }
            }
            __syncthreads();
            issue_chunk(cc + 2, Kb, Vb, KVb, tid);
        }
    }

    // ---- normalize and write output ----
    float inv[2] = {1.f / l_r[0], 1.f / l_r[1]};
    float* Ob = O + ((size_t)b * NS + q0) * ND;
    #pragma unroll
    for (int dc = 0; dc < 4; dc++)
        #pragma unroll
        for (int n8 = 0; n8 < 8; n8++)
            #pragma unroll
            for (int j = 0; j < 2; j++) {
                int row = RM + g + 8 * j;
                int col = dc * DC + wn * 64 + n8 * 8 + 2 * t;
                float2 v = make_float2(o[dc][n8][2 * j] * inv[j],
                                       o[dc][n8][2 * j + 1] * inv[j]);
                *reinterpret_cast<float2*>(Ob + (size_t)row * ND + col) = v;
            }
}

extern "C" void kernel_launch(void* const* d_in, const int* in_sizes, int n_in,
                              void* d_out, int out_size) {
    const float* q = (const float*)d_in[0];
    const float* k = (const float*)d_in[1];
    const float* v = (const float*)d_in[2];
    float* o = (float*)d_out;

    const int smem_bytes = SMEM_FLOATS * 4;   // 220160
    cudaFuncSetAttribute(attn_flash_tf32,
                         cudaFuncAttributeMaxDynamicSharedMemorySize, smem_bytes);
    dim3 grid(NS / BR, NB);
    attn_flash_tf32<<<grid, NTH, smem_bytes>>>(q, k, v, o);
}

// round 6
// speedup vs baseline: 1.4801x; 1.2006x over previous
#include <cuda_runtime.h>
#include <cstdint>
#include <math.h>

#define NB 8
#define NS 2048
#define ND 512
#define BR 64
#define BC 64
#define DC 128
#define NTH 512

#define QS_STRIDE 516   // 512+4 : stride%32==4 -> conflict-free A-frag loads
#define KS_STRIDE 132   // 128+4 : conflict-free K-as-B loads
#define VS_STRIDE 136   // 128+8 : conflict-free V-as-B loads
#define PS_STRIDE 68    // 64+4  : conflict-free P-as-A loads

// shared memory layout (in floats)
#define OFF_Q   0
#define SZ_Q    (BR*QS_STRIDE)            // 33024
#define SZ_KVB  (BC*VS_STRIDE)            // 8704 floats per buffer (max of K/V chunk)
#define OFF_KV  (OFF_Q + SZ_Q)
#define SZ_KV   (2*SZ_KVB)                // 17408 (double-buffered)
#define OFF_P   (OFF_KV + SZ_KV)
#define SZ_P    (BR*PS_STRIDE)            // 4352
#define OFF_RED (OFF_P + SZ_P)
#define SZ_RED  (8*BR)                    // 4 max partials + 4 sum partials
#define SMEM_FLOATS (OFF_RED + SZ_RED)    // 55296 floats = 221184 bytes

#define N_CHUNKS ((NS/BC)*8)              // 32 tiles * (4 K + 4 V) = 256 per CTA

__device__ __forceinline__ uint32_t f2tf(float x) {
    uint32_t u;
    asm("cvt.rna.tf32.f32 %0, %1;" : "=r"(u) : "f"(x));
    return u;
}

__device__ __forceinline__ uint32_t ldb(const float* p) {
    return __float_as_uint(*p);
}

__device__ __forceinline__ void mma8(float c[4],
                                     uint32_t a0, uint32_t a1, uint32_t a2, uint32_t a3,
                                     uint32_t b0, uint32_t b1) {
    asm volatile(
        "mma.sync.aligned.m16n8k8.row.col.f32.tf32.tf32.f32 "
        "{%0,%1,%2,%3},{%4,%5,%6,%7},{%8,%9},{%0,%1,%2,%3};\n"
        : "+f"(c[0]), "+f"(c[1]), "+f"(c[2]), "+f"(c[3])
        : "r"(a0), "r"(a1), "r"(a2), "r"(a3), "r"(b0), "r"(b1));
}

extern __shared__ float sm[];

// Issue async copy of flattened chunk index c (guarded), always commit a group
// so cp.async.wait_group counting stays uniform at the tail.
__device__ __forceinline__ void issue_chunk(int c, const float* Kb, const float* Vb,
                                            float* kvbase, int tid) {
    if (c < N_CHUNKS) {
        const int kt = c >> 3;
        const int ph = (c >> 2) & 1;          // 0 = K, 1 = V
        const int dc = c & 3;
        const float* src = (ph ? Vb : Kb) + (size_t)(kt * BC) * ND + dc * DC;
        const int stride = ph ? VS_STRIDE : KS_STRIDE;
        float* dst = kvbase + (c & 1) * SZ_KVB;
        #pragma unroll
        for (int i = 0; i < (BC * DC / 4) / NTH; i++) {   // 4 iters @512 thr
            int idx = tid + i * NTH;
            int row = idx >> 5;               // 32 float4 per row
            int c4  = idx & 31;
            const float* g = src + (size_t)row * ND + c4 * 4;
            uint32_t saddr = (uint32_t)__cvta_generic_to_shared(dst + row * stride + c4 * 4);
            asm volatile("cp.async.cg.shared.global [%0], [%1], 16;\n"
                         :: "r"(saddr), "l"(g));
        }
    }
    asm volatile("cp.async.commit_group;\n");
}

__device__ __forceinline__ void wait_prev() {
    asm volatile("cp.async.wait_group 1;\n" ::: "memory");
}

__global__ void __launch_bounds__(NTH, 1)
attn_flash_tf32(const float* __restrict__ Q,
                const float* __restrict__ K,
                const float* __restrict__ V,
                float* __restrict__ O) {
    const int b   = blockIdx.y;
    const int q0  = blockIdx.x * BR;
    const int tid = threadIdx.x;
    const int wid = tid >> 5;
    const int lane = tid & 31;
    const int wm = wid & 3;          // warp row: 4 groups of 16 rows
    const int wn = wid >> 2;         // warp col: 4 groups over N
    const int g = lane >> 2;         // groupID
    const int t = lane & 3;          // threadID-in-group
    const int RM = wm * 16;

    const float* Qb = Q + ((size_t)b * NS + q0) * ND;
    const float* Kb = K + (size_t)b * NS * ND;
    const float* Vb = V + (size_t)b * NS * ND;

    float* Qs  = sm + OFF_Q;
    float* KVb = sm + OFF_KV;
    float* Ps  = sm + OFF_P;
    float* red = sm + OFF_RED;

    // kick off the async pipeline before the (long) Q load
    issue_chunk(0, Kb, Vb, KVb, tid);
    issue_chunk(1, Kb, Vb, KVb, tid);

    // ---- load Q tile (64x512) into smem as RAW fp32 (split to tf32 at frag load) ----
    #pragma unroll
    for (int i = 0; i < (BR * ND / 4) / NTH; i++) {   // 16 iters
        int idx = tid + i * NTH;
        int row = idx >> 7;          // 128 float4 per row
        int c4  = idx & 127;
        float4 v = *reinterpret_cast<const float4*>(Qb + (size_t)row * ND + c4 * 4);
        *reinterpret_cast<float4*>(Qs + row * QS_STRIDE + c4 * 4) = v;
    }

    // output accumulators: o[dc][n8][4]; rows RM+g{,+8}; cols dc*128 + wn*32 + n8*8 + 2t{,+1}
    float o[4][4][4];
    #pragma unroll
    for (int a = 0; a < 4; a++)
        #pragma unroll
        for (int n = 0; n < 4; n++)
            #pragma unroll
            for (int c = 0; c < 4; c++) o[a][n][c] = 0.f;

    float m_r[2] = {-INFINITY, -INFINITY};
    float l_r[2] = {0.f, 0.f};

    for (int kt = 0; kt < NS / BC; kt++) {
        // ---- S = Q K^T (64x64), contraction over D in 4 async-pipelined chunks ----
        float sc[2][4];
        #pragma unroll
        for (int n = 0; n < 2; n++)
            #pragma unroll
            for (int c = 0; c < 4; c++) sc[n][c] = 0.f;

        for (int dc = 0; dc < ND / DC; dc++) {
            const int cc = kt * 8 + dc;
            wait_prev();
            __syncthreads();
            const float* Kc = KVb + (cc & 1) * SZ_KVB;

            #pragma unroll
            for (int kk = 0; kk < DC; kk += 8) {
                const float* qrow0 = Qs + (RM + g) * QS_STRIDE + dc * DC + kk + t;
                const float* qrow1 = Qs + (RM + g + 8) * QS_STRIDE + dc * DC + kk + t;
                uint32_t ah[4], al[4];
                {
                    float x0 = qrow0[0], x1 = qrow1[0], x2 = qrow0[4], x3 = qrow1[4];
                    ah[0] = f2tf(x0); al[0] = __float_as_uint(x0 - __uint_as_float(ah[0]));
                    ah[1] = f2tf(x1); al[1] = __float_as_uint(x1 - __uint_as_float(ah[1]));
                    ah[2] = f2tf(x2); al[2] = __float_as_uint(x2 - __uint_as_float(ah[2]));
                    ah[3] = f2tf(x3); al[3] = __float_as_uint(x3 - __uint_as_float(ah[3]));
                }
                #pragma unroll
                for (int n8 = 0; n8 < 2; n8++) {
                    int col = wn * 16 + n8 * 8 + g;   // kv index within tile
                    float k0 = Kc[col * KS_STRIDE + kk + t];
                    float k1 = Kc[col * KS_STRIDE + kk + t + 4];
                    uint32_t bh0 = f2tf(k0);
                    uint32_t bh1 = f2tf(k1);
                    uint32_t bl0 = __float_as_uint(k0 - __uint_as_float(bh0));
                    uint32_t bl1 = __float_as_uint(k1 - __uint_as_float(bh1));
                    // 3xTF32: hi*hi + lo*hi + hi*lo (lo fed raw; HW truncates)
                    mma8(sc[n8], ah[0], ah[1], ah[2], ah[3], bh0, bh1);
                    mma8(sc[n8], al[0], al[1], al[2], al[3], bh0, bh1);
                    mma8(sc[n8], ah[0], ah[1], ah[2], ah[3], bl0, bl1);
                }
            }
            __syncthreads();
            issue_chunk(cc + 2, Kb, Vb, KVb, tid);
        }

        // ---- online softmax: row max (4-way cross-warp over wn) ----
        #pragma unroll
        for (int j = 0; j < 2; j++) {
            float mx = fmaxf(sc[0][2 * j], sc[0][2 * j + 1]);
            mx = fmaxf(mx, fmaxf(sc[1][2 * j], sc[1][2 * j + 1]));
            mx = fmaxf(mx, __shfl_xor_sync(0xffffffffu, mx, 1));
            mx = fmaxf(mx, __shfl_xor_sync(0xffffffffu, mx, 2));
            if (t == 0) red[wn * BR + RM + g + 8 * j] = mx;
        }
        __syncthreads();

        float scale[2];
        #pragma unroll
        for (int j = 0; j < 2; j++) {
            int row = RM + g + 8 * j;
            float mt = fmaxf(fmaxf(red[row], red[BR + row]),
                             fmaxf(red[2 * BR + row], red[3 * BR + row]));
            float mnew = fmaxf(m_r[j], mt);
            scale[j] = __expf(m_r[j] - mnew);
            m_r[j] = mnew;
        }

        // ---- exponentiate, row-sum over the ROUNDED values, write P (tf32) ----
        float lsum_loc[2] = {0.f, 0.f};
        #pragma unroll
        for (int n8 = 0; n8 < 2; n8++) {
            #pragma unroll
            for (int j = 0; j < 2; j++) {
                float p0 = __expf(sc[n8][2 * j]     - m_r[j]);
                float p1 = __expf(sc[n8][2 * j + 1] - m_r[j]);
                uint32_t u0 = f2tf(p0), u1 = f2tf(p1);
                lsum_loc[j] += __uint_as_float(u0) + __uint_as_float(u1);
                int row = RM + g + 8 * j;
                int col = wn * 16 + n8 * 8 + 2 * t;
                *reinterpret_cast<uint2*>(Ps + row * PS_STRIDE + col) = make_uint2(u0, u1);
            }
        }
        #pragma unroll
        for (int j = 0; j < 2; j++) {
            lsum_loc[j] += __shfl_xor_sync(0xffffffffu, lsum_loc[j], 1);
            lsum_loc[j] += __shfl_xor_sync(0xffffffffu, lsum_loc[j], 2);
            if (t == 0) red[4 * BR + wn * BR + RM + g + 8 * j] = lsum_loc[j];
        }
        __syncthreads();   // Ps + sum partials visible

        #pragma unroll
        for (int j = 0; j < 2; j++) {
            int row = RM + g + 8 * j;
            float ls = (red[4 * BR + row] + red[5 * BR + row]) +
                       (red[6 * BR + row] + red[7 * BR + row]);
            l_r[j] = l_r[j] * scale[j] + ls;
        }

        // rescale existing O accumulators
        #pragma unroll
        for (int a = 0; a < 4; a++)
            #pragma unroll
            for (int n = 0; n < 4; n++) {
                o[a][n][0] *= scale[0];
                o[a][n][1] *= scale[0];
                o[a][n][2] *= scale[1];
                o[a][n][3] *= scale[1];
            }

        // ---- O += P V, async-pipelined V chunks (V fed raw; HW tf32 truncation) ----
        for (int dc = 0; dc < ND / DC; dc++) {
            const int cc = kt * 8 + 4 + dc;
            wait_prev();
            __syncthreads();
            const float* Vc = KVb + (cc & 1) * SZ_KVB;

            #pragma unroll
            for (int kk = 0; kk < BC; kk += 8) {
                const float* prow0 = Ps + (RM + g) * PS_STRIDE + kk + t;
                const float* prow1 = Ps + (RM + g + 8) * PS_STRIDE + kk + t;
                uint32_t a0 = ldb(prow0);
                uint32_t a1 = ldb(prow1);
                uint32_t a2 = ldb(prow0 + 4);
                uint32_t a3 = ldb(prow1 + 4);
                #pragma unroll
                for (int n8 = 0; n8 < 4; n8++) {
                    int col = wn * 32 + n8 * 8 + g;
                    uint32_t b0 = ldb(Vc + (kk + t) * VS_STRIDE + col);
                    uint32_t b1 = ldb(Vc + (kk + t + 4) * VS_STRIDE + col);
                    mma8(o[dc][n8], a0, a1, a2, a3, b0, b1);
                }
            }
            __syncthreads();
            issue_chunk(cc + 2, Kb, Vb, KVb, tid);
        }
    }

    // ---- normalize and write output ----
    float inv[2] = {1.f / l_r[0], 1.f / l_r[1]};
    float* Ob = O + ((size_t)b * NS + q0) * ND;
    #pragma unroll
    for (int dc = 0; dc < 4; dc++)
        #pragma unroll
        for (int n8 = 0; n8 < 4; n8++)
            #pragma unroll
            for (int j = 0; j < 2; j++) {
                int row = RM + g + 8 * j;
                int col = dc * DC + wn * 32 + n8 * 8 + 2 * t;
                float2 v = make_float2(o[dc][n8][2 * j] * inv[j],
                                       o[dc][n8][2 * j + 1] * inv[j]);
                *reinterpret_cast<float2*>(Ob + (size_t)row * ND + col) = v;
            }
}

extern "C" void kernel_launch(void* const* d_in, const int* in_sizes, int n_in,
                              void* d_out, int out_size) {
    const float* q = (const float*)d_in[0];
    const float* k = (const float*)d_in[1];
    const float* v = (const float*)d_in[2];
    float* o = (float*)d_out;

    const int smem_bytes = SMEM_FLOATS * 4;   // 221184
    cudaFuncSetAttribute(attn_flash_tf32,
                         cudaFuncAttributeMaxDynamicSharedMemorySize, smem_bytes);
    dim3 grid(NS / BR, NB);
    attn_flash_tf32<<<grid, NTH, smem_bytes>>>(q, k, v, o);
}